// round 1
// baseline (speedup 1.0000x reference)
#include <cuda_runtime.h>
#include <cstdint>

#define Bn 128
#define Tn 512
#define Dn 128

// Per-(b,i) contiguous support range of BlurMat column i (batch b).
__device__ int g_start[Bn * Tn];
__device__ int g_end[Bn * Tn];

// ---------------------------------------------------------------------------
// Kernel 0: vectorized passthrough copy of SeqtoBlur -> out[0 : B*T*T)
// ---------------------------------------------------------------------------
__global__ void copy_stb(const float4* __restrict__ src, float4* __restrict__ dst, int n4) {
    int idx = blockIdx.x * blockDim.x + threadIdx.x;
    int stride = gridDim.x * blockDim.x;
    for (int i = idx; i < n4; i += stride) dst[i] = src[i];
}

// ---------------------------------------------------------------------------
// Kernel 1: scan BlurMat columns for nonzero support range.
// Block b handles batch b; thread i owns column i. Row reads are coalesced
// (lane -> adjacent i). 128 blocks x 512 threads.
// ---------------------------------------------------------------------------
__global__ void scan_cols(const float* __restrict__ bm) {
    int b = blockIdx.x;
    int i = threadIdx.x;
    const float* col = bm + (size_t)b * Tn * Tn + i;
    int s = Tn, e = -1;
#pragma unroll 8
    for (int t = 0; t < Tn; ++t) {
        float v = __ldg(col + (size_t)t * Tn);
        if (v != 0.0f) {
            s = (t < s) ? t : s;
            e = t;
        }
    }
    g_start[b * Tn + i] = s;
    g_end[b * Tn + i]   = e;
}

// ---------------------------------------------------------------------------
// Kernel 2: sparse column-gather GEMM.
// Block (i, b), 128 threads = one per d. avged_seq[b,i,d] =
//   sum_{t in [start,end]} BlurMat[b,t,i] * seq[b,t,d].
// Writes the full region (zeros where support empty -> clears 0xAA poison,
// and handles the k==5 all-zero-BlurMat branch).
// ---------------------------------------------------------------------------
__global__ void spmm(const float* __restrict__ seq, const float* __restrict__ bm,
                     float* __restrict__ out_avged) {
    int i = blockIdx.x;
    int b = blockIdx.y;
    int d = threadIdx.x;
    int s = g_start[b * Tn + i];
    int e = g_end[b * Tn + i];
    const float* seqb = seq + (size_t)b * Tn * Dn + d;
    const float* col  = bm + (size_t)b * Tn * Tn + i;
    float acc = 0.0f;
#pragma unroll 2
    for (int t = s; t <= e; ++t) {
        float w = __ldg(col + (size_t)t * Tn);          // broadcast load
        acc = fmaf(w, __ldg(seqb + (size_t)t * Dn), acc); // coalesced row
    }
    out_avged[((size_t)b * Tn + i) * Dn + d] = acc;
}

// ---------------------------------------------------------------------------
// Kernel 3: ramps R / avged_R and avged_len tail.
// len arrays may be int32 or int64 (JAX x64 off -> int32 typical). Values are
// always >= 1, so for an int64 buffer the 32-bit word at index 1 is the high
// word of element 0 == 0; for int32 it is element 1 >= 1. Auto-detect.
// alen_mode: 0 = don't write avged_len, 1 = write as float, 2 = write as int64.
// ---------------------------------------------------------------------------
__global__ void ramps(const int* __restrict__ len_raw, const int* __restrict__ alen_raw,
                      float* __restrict__ R, float* __restrict__ aR,
                      float* __restrict__ alen_out, int alen_mode) {
    int b = blockIdx.x;
    int t = threadIdx.x;

    int ls = (len_raw[1] == 0) ? 2 : 1;
    int as_ = (alen_raw[1] == 0) ? 2 : 1;
    int l  = len_raw[b * ls];
    int al = alen_raw[b * as_];

    float lf = (float)l;
    float af = (float)al;
    R[b * Tn + t]  = (t < l)  ? ((float)(t + 1)) / fmaxf(lf, 1.0f) : 0.0f;
    aR[b * Tn + t] = (t < al) ? ((float)(t + 1)) / fmaxf(af, 1.0f) : 0.0f;

    if (t == 0) {
        if (alen_mode == 1) {
            alen_out[b] = (float)al;
        } else if (alen_mode == 2) {
            ((long long*)alen_out)[b] = (long long)al;
        }
    }
}

extern "C" void kernel_launch(void* const* d_in, const int* in_sizes, int n_in,
                              void* d_out, int out_size) {
    const float* seq       = (const float*)d_in[0];
    const int*   len_raw   = (const int*)d_in[1];
    const float* seqtoblur = (const float*)d_in[2];
    const float* blurmat   = (const float*)d_in[3];
    const int*   alen_raw  = (const int*)d_in[4];

    float* out = (float*)d_out;

    const size_t OFF_STB  = 0;
    const size_t OFF_AVG  = (size_t)Bn * Tn * Tn;                 // 33554432
    const size_t OFF_R    = OFF_AVG + (size_t)Bn * Tn * Dn;       // 41943040
    const size_t OFF_AR   = OFF_R + (size_t)Bn * Tn;              // 42008576
    const size_t OFF_ALEN = OFF_AR + (size_t)Bn * Tn;             // 42074112

    long long rem = (long long)out_size - (long long)OFF_ALEN;
    int alen_mode = 0;
    if (rem == Bn) alen_mode = 1;          // avged_len as float32
    else if (rem == 2 * Bn) alen_mode = 2; // avged_len as raw int64

    // 0) SeqtoBlur passthrough
    {
        int n4 = (int)(OFF_AVG / 4); // 8,388,608 float4s
        int threads = 256;
        int blocks = 4096; // grid-stride
        copy_stb<<<blocks, threads>>>((const float4*)(seqtoblur + OFF_STB),
                                      (float4*)(out + OFF_STB), n4);
    }

    // 1) Column support scan
    scan_cols<<<Bn, Tn>>>(blurmat);

    // 2) Sparse gather GEMM into avged_seq
    {
        dim3 grid(Tn, Bn);
        spmm<<<grid, Dn>>>(seq, blurmat, out + OFF_AVG);
    }

    // 3) Ramps + avged_len
    ramps<<<Bn, Tn>>>(len_raw, alen_raw, out + OFF_R, out + OFF_AR,
                      out + OFF_ALEN, alen_mode);
}

// round 2
// speedup vs baseline: 1.3236x; 1.3236x over previous
#include <cuda_runtime.h>
#include <cstdint>

#define Bn 128
#define Tn 512
#define Dn 128
#define COPY_N4 (Bn * Tn * Tn / 4)   // 8,388,608 float4
#define SCAN_BLOCKS 256              // 2 per batch, 256 cols each
#define RAMP_BLOCKS 128
#define COPY_BLOCKS 1664
#define TOTAL_BLOCKS (SCAN_BLOCKS + RAMP_BLOCKS + COPY_BLOCKS)

// Per-(b,i) contiguous support range of BlurMat column i (batch b).
__device__ int g_start[Bn * Tn];
__device__ int g_end[Bn * Tn];

// ---------------------------------------------------------------------------
// K1: fused independent work. Role by blockIdx.x:
//   [0,256):   column-support scan of BlurMat (coalesced row-major reads)
//   [256,384): ramps R / avged_R + avged_len tail
//   [384,...): SeqtoBlur passthrough copy (float4 grid-stride)
// All three are mutually independent -> run concurrently, keep DRAM saturated.
// ---------------------------------------------------------------------------
__global__ void __launch_bounds__(256) k1_fused(
    const float* __restrict__ seqtoblur, float* __restrict__ out_stb,
    const float* __restrict__ bm,
    const int* __restrict__ len_raw, const int* __restrict__ alen_raw,
    float* __restrict__ R, float* __restrict__ aR,
    float* __restrict__ alen_out, int alen_mode)
{
    int blk = blockIdx.x;
    int tid = threadIdx.x;

    if (blk < SCAN_BLOCKS) {
        // ---- scan ----
        int b = blk >> 1;
        int i = ((blk & 1) << 8) + tid;          // column index
        const float* col = bm + (size_t)b * Tn * Tn + i;
        int s = Tn, e = -1;
#pragma unroll 8
        for (int t = 0; t < Tn; ++t) {
            float v = __ldg(col + (size_t)t * Tn);
            if (v != 0.0f) { s = (t < s) ? t : s; e = t; }
        }
        g_start[b * Tn + i] = s;
        g_end[b * Tn + i]   = e;
        return;
    }

    if (blk < SCAN_BLOCKS + RAMP_BLOCKS) {
        // ---- ramps ----
        int b = blk - SCAN_BLOCKS;
        // int32 vs int64 auto-detect: values >= 1, so word[1]==0 <=> int64.
        int ls  = (len_raw[1]  == 0) ? 2 : 1;
        int as_ = (alen_raw[1] == 0) ? 2 : 1;
        int l  = len_raw[b * ls];
        int al = alen_raw[b * as_];
        float invl  = 1.0f / fmaxf((float)l,  1.0f);
        float inval = 1.0f / fmaxf((float)al, 1.0f);
#pragma unroll
        for (int t = tid; t < Tn; t += 256) {
            R[b * Tn + t]  = (t < l)  ? (float)(t + 1) * invl  : 0.0f;
            aR[b * Tn + t] = (t < al) ? (float)(t + 1) * inval : 0.0f;
        }
        if (tid == 0) {
            if (alen_mode == 1)      alen_out[b] = (float)al;
            else if (alen_mode == 2) ((long long*)alen_out)[b] = (long long)al;
        }
        return;
    }

    // ---- copy ----
    {
        int cblk = blk - (SCAN_BLOCKS + RAMP_BLOCKS);
        int idx = cblk * 256 + tid;
        int stride = COPY_BLOCKS * 256;
        const float4* s4 = (const float4*)seqtoblur;
        float4* d4 = (float4*)out_stb;
        for (int i = idx; i < COPY_N4; i += stride) d4[i] = s4[i];
    }
}

// ---------------------------------------------------------------------------
// K2: sparse column-gather. One WARP per output column (b,i); lane owns
// d4 = 4 consecutive d (float4 loads/stores). w is a warp-broadcast load
// (single L2 sector). Grid (Tn/4, Bn), 128 threads = 4 warps = 4 columns.
// Writes the full avged_seq region (zeros where support empty -> clears the
// 0xAA poison and handles the k==5 all-zero-BlurMat branch).
// ---------------------------------------------------------------------------
__global__ void __launch_bounds__(128) k2_spmm(
    const float* __restrict__ seq, const float* __restrict__ bm,
    float* __restrict__ out_avged)
{
    int warp = threadIdx.x >> 5;
    int lane = threadIdx.x & 31;
    int i = (blockIdx.x << 2) + warp;    // column
    int b = blockIdx.y;

    int s = g_start[b * Tn + i];
    int e = g_end[b * Tn + i];

    const float4* seqb = (const float4*)(seq + (size_t)b * Tn * Dn) + lane;
    const float*  col  = bm + (size_t)b * Tn * Tn + i;

    float4 acc = make_float4(0.f, 0.f, 0.f, 0.f);
    for (int t = s; t <= e; ++t) {
        float w = __ldg(col + (size_t)t * Tn);
        float4 v = __ldg(seqb + (size_t)t * (Dn / 4));
        acc.x = fmaf(w, v.x, acc.x);
        acc.y = fmaf(w, v.y, acc.y);
        acc.z = fmaf(w, v.z, acc.z);
        acc.w = fmaf(w, v.w, acc.w);
    }
    ((float4*)(out_avged + ((size_t)b * Tn + i) * Dn))[lane] = acc;
}

extern "C" void kernel_launch(void* const* d_in, const int* in_sizes, int n_in,
                              void* d_out, int out_size) {
    const float* seq       = (const float*)d_in[0];
    const int*   len_raw   = (const int*)d_in[1];
    const float* seqtoblur = (const float*)d_in[2];
    const float* blurmat   = (const float*)d_in[3];
    const int*   alen_raw  = (const int*)d_in[4];

    float* out = (float*)d_out;

    const size_t OFF_AVG  = (size_t)Bn * Tn * Tn;             // 33,554,432
    const size_t OFF_R    = OFF_AVG + (size_t)Bn * Tn * Dn;   // 41,943,040
    const size_t OFF_AR   = OFF_R + (size_t)Bn * Tn;          // 42,008,576
    const size_t OFF_ALEN = OFF_AR + (size_t)Bn * Tn;         // 42,074,112

    long long rem = (long long)out_size - (long long)OFF_ALEN;
    int alen_mode = 0;
    if (rem == Bn) alen_mode = 1;          // avged_len as float32
    else if (rem == 2 * Bn) alen_mode = 2; // avged_len as raw int64

    k1_fused<<<TOTAL_BLOCKS, 256>>>(seqtoblur, out,
                                    blurmat,
                                    len_raw, alen_raw,
                                    out + OFF_R, out + OFF_AR,
                                    out + OFF_ALEN, alen_mode);

    dim3 grid2(Tn / 4, Bn);
    k2_spmm<<<grid2, 128>>>(seq, blurmat, out + OFF_AVG);
}